// round 7
// baseline (speedup 1.0000x reference)
#include <cuda_runtime.h>
#include <math.h>

#define SEQ 20
#define H   128
#define NC  100000

// ---------------- device scratch (no allocations allowed) ----------------
__device__ float g_Xf[SEQ][4*H];          // x @ Wih_f^T + bih_f + bhh_f
__device__ float g_Xb[SEQ][4*H];          // x[rev] @ Wih_b^T + biases
__device__ float g_comb[SEQ][2*H];        // [fwd_h, bwd_h]
__device__ float g_Xl[SEQ][8*H];          // comb @ Wih_l^T + biases
__device__ float g_hl[SEQ][2*H];          // layer-2 hidden states
__device__ float g_gates1[2][SEQ][4*H];   // per-step gate buffers (layer 1)
__device__ float g_gates2[SEQ][8*H];      // per-step gate buffers (layer 2)
__device__ int   g_bar1[2][SEQ];          // per-step arrival counters, layer 1
__device__ int   g_bar2[SEQ];             // per-step arrival counters, layer 2

// ---------------- helpers ----------------
__device__ __forceinline__ void fma2(unsigned long long& d,
                                     unsigned long long a, unsigned long long b) {
    // packed fp32x2 FMA (Blackwell FFMA2) — only reachable via PTX
    asm("fma.rn.f32x2 %0, %1, %2, %0;" : "+l"(d) : "l"(a), "l"(b));
}
__device__ __forceinline__ float sum2(unsigned long long v) {
    float lo, hi;
    asm("mov.b64 {%0, %1}, %2;" : "=f"(lo), "=f"(hi) : "l"(v));
    return lo + hi;
}
__device__ __forceinline__ float sigm(float x) { return 1.0f / (1.0f + expf(-x)); }

// =====================================================================
// proj_kernel<K>: out[t][n] = sum_k A[t][k]*W[n][k] + b1[n] (+ b2[n])
// for t in [0,20). One block handles a 64-wide n-tile; W tile staged in
// padded shared (stride = K+4 -> conflict-free LDS.128 across rows).
// a_sel: 0=A param, 1=g_comb, 2=g_hl.  out_sel: 0=g_Xf 1=g_Xb 2=g_Xl 3=param.
// rev: read A rows reversed (backward LSTM input).
// =====================================================================
template<int K>
__global__ void proj_kernel(const float* __restrict__ Apar,
                            const float* __restrict__ W,
                            const float* __restrict__ b1,
                            const float* __restrict__ b2,
                            float* __restrict__ Opar,
                            int N, int a_sel, int out_sel, int rev)
{
    extern __shared__ float sm[];
    const int stride = K + 4;
    float* sW = sm;                    // 64 * stride
    float* sA = sm + 64 * stride;      // SEQ * K (16B aligned: 64*stride*4 % 16 == 0)

    const int tid   = threadIdx.x;     // 128 threads
    const int nbase = blockIdx.x * 64;

    const float* A = (a_sel == 0) ? Apar
                   : (a_sel == 1) ? &g_comb[0][0] : &g_hl[0][0];
    float* out = (out_sel == 0) ? &g_Xf[0][0]
               : (out_sel == 1) ? &g_Xb[0][0]
               : (out_sel == 2) ? &g_Xl[0][0] : Opar;

    // stage A (optionally time-reversed)
    for (int idx = tid; idx < SEQ * K; idx += blockDim.x) {
        int t = idx / K, k = idx - t * K;
        sA[idx] = rev ? A[(SEQ - 1 - t) * K + k] : A[idx];
    }
    // stage 64 x K weight tile, coalesced float4, zero-fill OOB rows
    const int k4n = K >> 2;
    const float4* W4 = reinterpret_cast<const float4*>(W);
    for (int idx = tid; idx < 64 * k4n; idx += blockDim.x) {
        int r = idx / k4n, k4 = idx - r * k4n;
        int n = nbase + r;
        float4 v = (n < N) ? W4[(long)n * k4n + k4] : make_float4(0.f, 0.f, 0.f, 0.f);
        *reinterpret_cast<float4*>(&sW[r * stride + 4 * k4]) = v;
    }
    __syncthreads();

    const int nl = tid & 63;                 // local n
    const int th = (tid >> 6) * (SEQ / 2);   // t-half: rows 0..9 or 10..19

    unsigned long long acc[SEQ / 2];
    #pragma unroll
    for (int i = 0; i < SEQ / 2; i++) acc[i] = 0ull;

    const float* wrow = &sW[nl * stride];
    #pragma unroll 2
    for (int k4 = 0; k4 < k4n; k4++) {
        ulonglong2 w = *reinterpret_cast<const ulonglong2*>(&wrow[4 * k4]);
        #pragma unroll
        for (int tt = 0; tt < SEQ / 2; tt++) {
            ulonglong2 a = *reinterpret_cast<const ulonglong2*>(&sA[(th + tt) * K + 4 * k4]);
            fma2(acc[tt], w.x, a.x);
            fma2(acc[tt], w.y, a.y);
        }
    }
    const int n = nbase + nl;
    if (n < N) {
        float bias = b1[n] + (b2 ? b2[n] : 0.0f);
        #pragma unroll
        for (int tt = 0; tt < SEQ / 2; tt++)
            out[(long)(th + tt) * N + n] = sum2(acc[tt]) + bias;
    }
}

// =====================================================================
__global__ void zero_bar_kernel()
{
    int tid = threadIdx.x;
    if (tid < 2 * SEQ) ((int*)g_bar1)[tid] = 0;
    if (tid < SEQ)     g_bar2[tid] = 0;
}

// =====================================================================
// rec1: layer-1 LSTM recurrences. 8 blocks: dir = blk>>2, slice = blk&3.
// Each block owns 128 gate rows with its Whh slice resident in shared.
// Per step: gate slice -> global, spin barrier (4 blocks/dir), every block
// redundantly computes the h/c update. slice 0 writes g_comb.
// =====================================================================
__global__ void rec1_kernel(const float* __restrict__ Whh_f,
                            const float* __restrict__ Whh_b,
                            const float* __restrict__ h0f, const float* __restrict__ c0f,
                            const float* __restrict__ h0b, const float* __restrict__ c0b)
{
    extern __shared__ float sm[];
    const int stride = H + 4;          // 132 (== 4 mod 32 -> conflict-free)
    float* sW = sm;                    // 128 * 132
    __shared__ __align__(16) float sh[H];
    __shared__ __align__(16) float sc[H];

    const int tid = threadIdx.x;       // 128
    const int d = blockIdx.x >> 2;     // direction
    const int s = blockIdx.x & 3;      // row slice
    const int rowbase = s * 128;

    const float* Whh = d ? Whh_b : Whh_f;
    const float* h0  = d ? h0b : h0f;
    const float* c0  = d ? c0b : c0f;
    const float* X   = d ? &g_Xb[0][0] : &g_Xf[0][0];
    float* gates = &g_gates1[d][0][0];

    // stage Whh rows [rowbase, rowbase+128)
    const float4* W4 = reinterpret_cast<const float4*>(Whh);
    for (int idx = tid; idx < 128 * (H / 4); idx += blockDim.x) {
        int r = idx >> 5, k4 = idx & 31;
        *reinterpret_cast<float4*>(&sW[r * stride + 4 * k4]) = W4[(rowbase + r) * (H / 4) + k4];
    }
    sh[tid] = h0[tid];
    sc[tid] = c0[tid];
    __syncthreads();

    for (int t = 0; t < SEQ; t++) {
        // gate[row] = X[t][row] + Whh[row,:] . h
        unsigned long long a0 = 0ull, a1 = 0ull;
        const float* wrow = &sW[tid * stride];
        #pragma unroll
        for (int k4 = 0; k4 < H / 4; k4++) {
            ulonglong2 w = *reinterpret_cast<const ulonglong2*>(&wrow[4 * k4]);
            ulonglong2 h = *reinterpret_cast<const ulonglong2*>(&sh[4 * k4]);
            if (k4 & 1) { fma2(a1, w.x, h.x); fma2(a1, w.y, h.y); }
            else        { fma2(a0, w.x, h.x); fma2(a0, w.y, h.y); }
        }
        const int row = rowbase + tid;
        gates[t * 4 * H + row] = sum2(a0) + sum2(a1) + X[t * 4 * H + row];

        __threadfence();
        __syncthreads();
        if (tid == 0) {
            atomicAdd(&g_bar1[d][t], 1);
            while (*((volatile int*)&g_bar1[d][t]) < 4) { }
        }
        __syncthreads();
        __threadfence();

        // redundant full h/c update in every block (needs all 4 gates)
        {
            const float* gt = &gates[t * 4 * H];
            float gi = gt[tid], gf = gt[H + tid], gg = gt[2 * H + tid], go = gt[3 * H + tid];
            float c = sigm(gf) * sc[tid] + sigm(gi) * tanhf(gg);
            float h = sigm(go) * tanhf(c);
            sc[tid] = c;
            sh[tid] = h;
            if (s == 0) g_comb[t][d * H + tid] = h;   // scan order kept (bwd NOT flipped)
        }
        __syncthreads();
    }
}

// =====================================================================
// rec2: layer-2 LSTM (hidden 2H=256, 8H=1024 gate rows). 16 blocks x 64 rows,
// Whh_l slice (64 x 256 fp32 = 64KB) resident in shared.
// =====================================================================
__global__ void rec2_kernel(const float* __restrict__ Whh_l,
                            const float* __restrict__ h0l,
                            const float* __restrict__ c0l)
{
    extern __shared__ float sm[];
    const int K2 = 2 * H;              // 256
    const int stride = K2 + 4;         // 260
    float* sW = sm;                    // 64 * 260
    __shared__ __align__(16) float sh[2 * H];
    __shared__ __align__(16) float sc[2 * H];

    const int tid = threadIdx.x;       // 64
    const int rowbase = blockIdx.x * 64;

    const float4* W4 = reinterpret_cast<const float4*>(Whh_l);
    for (int idx = tid; idx < 64 * (K2 / 4); idx += blockDim.x) {
        int r = idx >> 6, k4 = idx & 63;
        *reinterpret_cast<float4*>(&sW[r * stride + 4 * k4]) = W4[(rowbase + r) * (K2 / 4) + k4];
    }
    #pragma unroll
    for (int i = 0; i < 4; i++) {
        sh[tid + i * 64] = h0l[tid + i * 64];
        sc[tid + i * 64] = c0l[tid + i * 64];
    }
    __syncthreads();

    for (int t = 0; t < SEQ; t++) {
        unsigned long long acc[4] = {0ull, 0ull, 0ull, 0ull};
        const float* wrow = &sW[tid * stride];
        #pragma unroll
        for (int k4 = 0; k4 < K2 / 4; k4++) {
            ulonglong2 w = *reinterpret_cast<const ulonglong2*>(&wrow[4 * k4]);
            ulonglong2 h = *reinterpret_cast<const ulonglong2*>(&sh[4 * k4]);
            fma2(acc[k4 & 3], w.x, h.x);
            fma2(acc[k4 & 3], w.y, h.y);
        }
        const int row = rowbase + tid;
        g_gates2[t][row] = sum2(acc[0]) + sum2(acc[1]) + sum2(acc[2]) + sum2(acc[3])
                         + g_Xl[t][row];

        __threadfence();
        __syncthreads();
        if (tid == 0) {
            atomicAdd(&g_bar2[t], 1);
            while (*((volatile int*)&g_bar2[t]) < 16) { }
        }
        __syncthreads();
        __threadfence();

        // redundant update of 256-dim h/c: 4 elements per thread
        const float* gt = &g_gates2[t][0];
        #pragma unroll
        for (int i = 0; i < 4; i++) {
            int k = tid + i * 64;
            float gi = gt[k], gf = gt[K2 + k], gg = gt[2 * K2 + k], go = gt[3 * K2 + k];
            float c = sigm(gf) * sc[k] + sigm(gi) * tanhf(gg);
            float h = sigm(go) * tanhf(c);
            sc[k] = c;
            sh[k] = h;
            if (blockIdx.x == 0) g_hl[t][k] = h;
        }
        __syncthreads();
    }
}

// =====================================================================
extern "C" void kernel_launch(void* const* d_in, const int* in_sizes, int n_in,
                              void* d_out, int out_size)
{
    const float* x     = (const float*)d_in[0];
    const float* h0f   = (const float*)d_in[1];
    const float* c0f   = (const float*)d_in[2];
    const float* h0b   = (const float*)d_in[3];
    const float* c0b   = (const float*)d_in[4];
    const float* h0l   = (const float*)d_in[5];
    const float* c0l   = (const float*)d_in[6];
    const float* Wih_f = (const float*)d_in[7];
    const float* Whh_f = (const float*)d_in[8];
    const float* bih_f = (const float*)d_in[9];
    const float* bhh_f = (const float*)d_in[10];
    const float* Wih_b = (const float*)d_in[11];
    const float* Whh_b = (const float*)d_in[12];
    const float* bih_b = (const float*)d_in[13];
    const float* bhh_b = (const float*)d_in[14];
    const float* Wih_l = (const float*)d_in[15];
    const float* Whh_l = (const float*)d_in[16];
    const float* bih_l = (const float*)d_in[17];
    const float* bhh_l = (const float*)d_in[18];
    const float* Wlin  = (const float*)d_in[19];
    const float* blin  = (const float*)d_in[20];
    float* out = (float*)d_out;

    const int smem_p128 = (64 * (128 + 4) + SEQ * 128) * 4;   // 44032
    const int smem_p256 = (64 * (256 + 4) + SEQ * 256) * 4;   // 87040
    const int smem_r1   = 128 * (128 + 4) * 4;                // 67584
    const int smem_r2   = 64 * (256 + 4) * 4;                 // 66560

    cudaFuncSetAttribute(proj_kernel<128>, cudaFuncAttributeMaxDynamicSharedMemorySize, smem_p128);
    cudaFuncSetAttribute(proj_kernel<256>, cudaFuncAttributeMaxDynamicSharedMemorySize, smem_p256);
    cudaFuncSetAttribute(rec1_kernel,      cudaFuncAttributeMaxDynamicSharedMemorySize, smem_r1);
    cudaFuncSetAttribute(rec2_kernel,      cudaFuncAttributeMaxDynamicSharedMemorySize, smem_r2);

    // 1) x-projections for both layer-1 directions (parallel GEMMs)
    proj_kernel<128><<<8, 128, smem_p128>>>(x, Wih_f, bih_f, bhh_f, nullptr,
                                            4 * H, /*a*/0, /*out*/0, /*rev*/0);
    proj_kernel<128><<<8, 128, smem_p128>>>(x, Wih_b, bih_b, bhh_b, nullptr,
                                            4 * H, 0, 1, 1);
    // 2) reset spin-barrier counters (graph-replay safe)
    zero_bar_kernel<<<1, 64>>>();
    // 3) layer-1 recurrences (fwd + bwd in lockstep, 4 blocks each)
    rec1_kernel<<<8, 128, smem_r1>>>(Whh_f, Whh_b, h0f, c0f, h0b, c0b);
    // 4) layer-2 x-projection: comb @ Wih_l^T + biases
    proj_kernel<256><<<16, 128, smem_p256>>>(nullptr, Wih_l, bih_l, bhh_l, nullptr,
                                             8 * H, 1, 2, 0);
    // 5) layer-2 recurrence
    rec2_kernel<<<16, 64, smem_r2>>>(Whh_l, h0l, c0l);
    // 6) final linear head: [20,100000] = hl @ Wlin^T + blin
    proj_kernel<256><<<(NC + 63) / 64, 128, smem_p256>>>(nullptr, Wlin, blin, nullptr,
                                                         out, NC, 2, 3, 0);
}

// round 9
// speedup vs baseline: 1.4200x; 1.4200x over previous
#include <cuda_runtime.h>
#include <math.h>

#define SEQ 20
#define H   128
#define NC  100000

// ---------------- device scratch (no allocations allowed) ----------------
__device__ float g_Xf[SEQ][4*H];          // x @ Wih_f^T + bih_f + bhh_f
__device__ float g_Xb[SEQ][4*H];          // x[rev] @ Wih_b^T + biases
__device__ float g_comb[SEQ][2*H];        // [fwd_h, bwd_h]
__device__ float g_Xl[SEQ][8*H];          // comb @ Wih_l^T + biases
__device__ float g_hl[SEQ][2*H];          // layer-2 hidden states

// ---------------- helpers ----------------
__device__ __forceinline__ void fma2(unsigned long long& d,
                                     unsigned long long a, unsigned long long b) {
    asm("fma.rn.f32x2 %0, %1, %2, %0;" : "+l"(d) : "l"(a), "l"(b));
}
__device__ __forceinline__ float sum2(unsigned long long v) {
    float lo, hi;
    asm("mov.b64 {%0, %1}, %2;" : "=f"(lo), "=f"(hi) : "l"(v));
    return lo + hi;
}
__device__ __forceinline__ float sigm(float x) { return 1.0f / (1.0f + expf(-x)); }

__device__ __forceinline__ unsigned smem_u32(const void* p) {
    return (unsigned)__cvta_generic_to_shared(p);
}
__device__ __forceinline__ unsigned mapa_u32(unsigned addr, unsigned rank) {
    unsigned d;
    asm("mapa.shared::cluster.u32 %0, %1, %2;" : "=r"(d) : "r"(addr), "r"(rank));
    return d;
}
__device__ __forceinline__ void st_remote_f32(unsigned addr, float v) {
    asm volatile("st.shared::cluster.f32 [%0], %1;" :: "r"(addr), "f"(v));
}
__device__ __forceinline__ unsigned ctarank() {
    unsigned r; asm("mov.u32 %0, %%cluster_ctarank;" : "=r"(r)); return r;
}
#define CLUSTER_SYNC() do { \
    asm volatile("barrier.cluster.arrive.aligned;" ::: "memory"); \
    asm volatile("barrier.cluster.wait.aligned;"   ::: "memory"); } while (0)

// =====================================================================
// proj_kernel<K>: out[t][n] = sum_k A[t][k]*W[n][k] + b1[n] (+ b2[n])
// One block = 64-wide n-tile; padded smem (stride = K+4) conflict-free.
// a_sel: 0=A param, 1=g_comb, 2=g_hl.  out_sel: 0=g_Xf 1=g_Xb 2=g_Xl 3=param.
// =====================================================================
template<int K>
__global__ void proj_kernel(const float* __restrict__ Apar,
                            const float* __restrict__ W,
                            const float* __restrict__ b1,
                            const float* __restrict__ b2,
                            float* __restrict__ Opar,
                            int N, int a_sel, int out_sel, int rev)
{
    extern __shared__ float sm[];
    const int stride = K + 4;
    float* sW = sm;                    // 64 * stride
    float* sA = sm + 64 * stride;      // SEQ * K

    const int tid   = threadIdx.x;     // 128
    const int nbase = blockIdx.x * 64;

    const float* A = (a_sel == 0) ? Apar
                   : (a_sel == 1) ? &g_comb[0][0] : &g_hl[0][0];
    float* out = (out_sel == 0) ? &g_Xf[0][0]
               : (out_sel == 1) ? &g_Xb[0][0]
               : (out_sel == 2) ? &g_Xl[0][0] : Opar;

    for (int idx = tid; idx < SEQ * K; idx += blockDim.x) {
        int t = idx / K, k = idx - t * K;
        sA[idx] = rev ? A[(SEQ - 1 - t) * K + k] : A[idx];
    }
    const int k4n = K >> 2;
    const float4* W4 = reinterpret_cast<const float4*>(W);
    for (int idx = tid; idx < 64 * k4n; idx += blockDim.x) {
        int r = idx / k4n, k4 = idx - r * k4n;
        int n = nbase + r;
        float4 v = (n < N) ? W4[(long)n * k4n + k4] : make_float4(0.f, 0.f, 0.f, 0.f);
        *reinterpret_cast<float4*>(&sW[r * stride + 4 * k4]) = v;
    }
    __syncthreads();

    const int nl = tid & 63;
    const int th = (tid >> 6) * (SEQ / 2);

    unsigned long long acc[SEQ / 2];
    #pragma unroll
    for (int i = 0; i < SEQ / 2; i++) acc[i] = 0ull;

    const float* wrow = &sW[nl * stride];
    #pragma unroll 2
    for (int k4 = 0; k4 < k4n; k4++) {
        ulonglong2 w = *reinterpret_cast<const ulonglong2*>(&wrow[4 * k4]);
        #pragma unroll
        for (int tt = 0; tt < SEQ / 2; tt++) {
            ulonglong2 a = *reinterpret_cast<const ulonglong2*>(&sA[(th + tt) * K + 4 * k4]);
            fma2(acc[tt], w.x, a.x);
            fma2(acc[tt], w.y, a.y);
        }
    }
    const int n = nbase + nl;
    if (n < N) {
        float bias = b1[n] + (b2 ? b2[n] : 0.0f);
        #pragma unroll
        for (int tt = 0; tt < SEQ / 2; tt++)
            out[(long)(th + tt) * N + n] = sum2(acc[tt]) + bias;
    }
}

// =====================================================================
// rec1: layer-1 LSTM, cluster of 4 CTAs per direction (grid 8).
// CTA rank s owns h-elements j in [32s,32s+32) and gate rows {g*128+j}.
// Whh slice (128x128) + X addends staged in smem; h exchanged via DSMEM
// stores into a double-buffered sh[]; one cluster barrier per step.
// =====================================================================
__global__ void __cluster_dims__(4, 1, 1)
rec1_kernel(const float* __restrict__ Whh_f,
            const float* __restrict__ Whh_b,
            const float* __restrict__ h0f, const float* __restrict__ c0f,
            const float* __restrict__ h0b, const float* __restrict__ c0b)
{
    extern __shared__ float sm[];
    const int stride = H + 4;            // 132 -> conflict-free
    float* sW = sm;                      // 128 * 132
    float* sX = sm + 128 * stride;       // SEQ * 128 (own rows)
    __shared__ __align__(16) float sh[2][H];
    __shared__ float sg[128];
    __shared__ float sc[32];

    const int tid = threadIdx.x;         // 256
    const unsigned s = ctarank();        // 0..3
    const int d  = blockIdx.x >> 2;      // direction (clusters are contiguous)
    const int j0 = (int)s * 32;

    const float* Whh = d ? Whh_b : Whh_f;
    const float* h0  = d ? h0b : h0f;
    const float* c0  = d ? c0b : c0f;
    const float* X   = d ? &g_Xb[0][0] : &g_Xf[0][0];

    // stage Whh rows for this CTA's 128 gate rows (row = g*128 + j0 + lane)
    const float4* W4 = reinterpret_cast<const float4*>(Whh);
    for (int idx = tid; idx < 128 * 32; idx += 256) {
        int rr = idx >> 5, k4 = idx & 31;
        int row = ((rr >> 5) << 7) + j0 + (rr & 31);
        *reinterpret_cast<float4*>(&sW[rr * stride + 4 * k4]) = W4[row * 32 + k4];
    }
    // stage X addends for all 20 steps (own rows only)
    for (int idx = tid; idx < SEQ * 128; idx += 256) {
        int ts = idx >> 7, tt = idx & 127;
        int row = ((tt >> 5) << 7) + j0 + (tt & 31);
        sX[idx] = X[ts * 4 * H + row];
    }
    if (tid < H)  sh[0][tid] = h0[tid];
    if (tid < 32) sc[tid]    = c0[j0 + tid];
    __syncthreads();

    int p = 0;
    for (int t = 0; t < SEQ; t++) {
        if (tid < 128) {
            const float* wr = &sW[tid * stride];
            const float* hb = sh[p];
            unsigned long long a[4] = {0ull, 0ull, 0ull, 0ull};
            #pragma unroll
            for (int k4 = 0; k4 < 32; k4++) {
                ulonglong2 w = *reinterpret_cast<const ulonglong2*>(&wr[4 * k4]);
                ulonglong2 h = *reinterpret_cast<const ulonglong2*>(&hb[4 * k4]);
                fma2(a[(k4 & 1) << 1],       w.x, h.x);
                fma2(a[((k4 & 1) << 1) | 1], w.y, h.y);
            }
            sg[tid] = sum2(a[0]) + sum2(a[1]) + sum2(a[2]) + sum2(a[3]) + sX[t * 128 + tid];
        }
        __syncthreads();
        if (tid < 32) {
            float gi = sg[tid], gf = sg[32 + tid], gg = sg[64 + tid], go = sg[96 + tid];
            float c = sigm(gf) * sc[tid] + sigm(gi) * tanhf(gg);
            float h = sigm(go) * tanhf(c);
            sc[tid] = c;
            unsigned la = smem_u32(&sh[p ^ 1][j0 + tid]);
            #pragma unroll
            for (unsigned r = 0; r < 4; r++) st_remote_f32(mapa_u32(la, r), h);
            g_comb[t][d * H + j0 + tid] = h;   // bwd kept in reversed-scan order
        }
        CLUSTER_SYNC();                        // release/acquire orders DSMEM stores
        p ^= 1;
    }
}

// =====================================================================
// rec2: layer-2 LSTM (hidden 256), single cluster of 8 CTAs (grid 8).
// CTA rank s owns h-elems [32s,32s+32), gate rows {g*256 + j}.
// Whh_l slice 128x256 = 128KB in smem.
// =====================================================================
__global__ void __cluster_dims__(8, 1, 1)
rec2_kernel(const float* __restrict__ Whh_l,
            const float* __restrict__ h0l,
            const float* __restrict__ c0l)
{
    extern __shared__ float sm[];
    const int K2 = 2 * H;                // 256
    const int stride = K2 + 4;           // 260 -> conflict-free
    float* sW = sm;                      // 128 * 260
    float* sX = sm + 128 * stride;       // SEQ * 128 (own rows)
    __shared__ __align__(16) float sh[2][2 * H];
    __shared__ float sg[128];
    __shared__ float sc[32];

    const int tid = threadIdx.x;         // 256
    const unsigned s = ctarank();        // 0..7
    const int j0 = (int)s * 32;

    const float4* W4 = reinterpret_cast<const float4*>(Whh_l);
    for (int idx = tid; idx < 128 * 64; idx += 256) {
        int rr = idx >> 6, k4 = idx & 63;
        int row = ((rr >> 5) << 8) + j0 + (rr & 31);
        *reinterpret_cast<float4*>(&sW[rr * stride + 4 * k4]) = W4[row * 64 + k4];
    }
    for (int idx = tid; idx < SEQ * 128; idx += 256) {
        int ts = idx >> 7, tt = idx & 127;
        int row = ((tt >> 5) << 8) + j0 + (tt & 31);
        sX[idx] = g_Xl[ts][row];
    }
    if (tid < K2) sh[0][tid] = h0l[tid];
    if (tid < 32) sc[tid]    = c0l[j0 + tid];
    __syncthreads();

    int p = 0;
    for (int t = 0; t < SEQ; t++) {
        if (tid < 128) {
            const float* wr = &sW[tid * stride];
            const float* hb = sh[p];
            unsigned long long a[8];
            #pragma unroll
            for (int i = 0; i < 8; i++) a[i] = 0ull;
            #pragma unroll
            for (int k4 = 0; k4 < 64; k4++) {
                ulonglong2 w = *reinterpret_cast<const ulonglong2*>(&wr[4 * k4]);
                ulonglong2 h = *reinterpret_cast<const ulonglong2*>(&hb[4 * k4]);
                fma2(a[(k4 & 3) << 1],       w.x, h.x);
                fma2(a[((k4 & 3) << 1) | 1], w.y, h.y);
            }
            float dot = sum2(a[0]) + sum2(a[1]) + sum2(a[2]) + sum2(a[3])
                      + sum2(a[4]) + sum2(a[5]) + sum2(a[6]) + sum2(a[7]);
            sg[tid] = dot + sX[t * 128 + tid];
        }
        __syncthreads();
        if (tid < 32) {
            float gi = sg[tid], gf = sg[32 + tid], gg = sg[64 + tid], go = sg[96 + tid];
            float c = sigm(gf) * sc[tid] + sigm(gi) * tanhf(gg);
            float h = sigm(go) * tanhf(c);
            sc[tid] = c;
            unsigned la = smem_u32(&sh[p ^ 1][j0 + tid]);
            #pragma unroll
            for (unsigned r = 0; r < 8; r++) st_remote_f32(mapa_u32(la, r), h);
            g_hl[t][j0 + tid] = h;
        }
        CLUSTER_SYNC();
        p ^= 1;
    }
}

// =====================================================================
extern "C" void kernel_launch(void* const* d_in, const int* in_sizes, int n_in,
                              void* d_out, int out_size)
{
    const float* x     = (const float*)d_in[0];
    const float* h0f   = (const float*)d_in[1];
    const float* c0f   = (const float*)d_in[2];
    const float* h0b   = (const float*)d_in[3];
    const float* c0b   = (const float*)d_in[4];
    const float* h0l   = (const float*)d_in[5];
    const float* c0l   = (const float*)d_in[6];
    const float* Wih_f = (const float*)d_in[7];
    const float* Whh_f = (const float*)d_in[8];
    const float* bih_f = (const float*)d_in[9];
    const float* bhh_f = (const float*)d_in[10];
    const float* Wih_b = (const float*)d_in[11];
    const float* Whh_b = (const float*)d_in[12];
    const float* bih_b = (const float*)d_in[13];
    const float* bhh_b = (const float*)d_in[14];
    const float* Wih_l = (const float*)d_in[15];
    const float* Whh_l = (const float*)d_in[16];
    const float* bih_l = (const float*)d_in[17];
    const float* bhh_l = (const float*)d_in[18];
    const float* Wlin  = (const float*)d_in[19];
    const float* blin  = (const float*)d_in[20];
    float* out = (float*)d_out;

    const int smem_p128 = (64 * (128 + 4) + SEQ * 128) * 4;   // 44032
    const int smem_p256 = (64 * (256 + 4) + SEQ * 256) * 4;   // 87040
    const int smem_r1   = (128 * (128 + 4) + SEQ * 128) * 4;  // 77824
    const int smem_r2   = (128 * (256 + 4) + SEQ * 128) * 4;  // 143360

    cudaFuncSetAttribute(proj_kernel<128>, cudaFuncAttributeMaxDynamicSharedMemorySize, smem_p128);
    cudaFuncSetAttribute(proj_kernel<256>, cudaFuncAttributeMaxDynamicSharedMemorySize, smem_p256);
    cudaFuncSetAttribute(rec1_kernel,      cudaFuncAttributeMaxDynamicSharedMemorySize, smem_r1);
    cudaFuncSetAttribute(rec2_kernel,      cudaFuncAttributeMaxDynamicSharedMemorySize, smem_r2);

    // 1) x-projections for both layer-1 directions
    proj_kernel<128><<<8, 128, smem_p128>>>(x, Wih_f, bih_f, bhh_f, nullptr,
                                            4 * H, 0, 0, 0);
    proj_kernel<128><<<8, 128, smem_p128>>>(x, Wih_b, bih_b, bhh_b, nullptr,
                                            4 * H, 0, 1, 1);
    // 2) layer-1 recurrences (2 clusters of 4, one per direction)
    rec1_kernel<<<8, 256, smem_r1>>>(Whh_f, Whh_b, h0f, c0f, h0b, c0b);
    // 3) layer-2 x-projection
    proj_kernel<256><<<16, 128, smem_p256>>>(nullptr, Wih_l, bih_l, bhh_l, nullptr,
                                             8 * H, 1, 2, 0);
    // 4) layer-2 recurrence (1 cluster of 8)
    rec2_kernel<<<8, 256, smem_r2>>>(Whh_l, h0l, c0l);
    // 5) final linear head
    proj_kernel<256><<<(NC + 63) / 64, 128, smem_p256>>>(nullptr, Wlin, blin, nullptr,
                                                         out, NC, 2, 3, 0);
}

// round 10
// speedup vs baseline: 2.0221x; 1.4240x over previous
#include <cuda_runtime.h>
#include <math.h>

#define SEQ 20
#define H   128
#define NC  100000

// ---------------- device scratch (no allocations allowed) ----------------
__device__ float g_Xf[SEQ][4*H];          // x @ Wih_f^T + bih_f + bhh_f
__device__ float g_Xb[SEQ][4*H];          // x[rev] @ Wih_b^T + biases
__device__ float g_comb[SEQ][2*H];        // [fwd_h, bwd_h]
__device__ float g_Xl[SEQ][8*H];          // comb @ Wih_l^T + biases
__device__ float g_hl[SEQ][2*H];          // layer-2 hidden states

// ---------------- helpers ----------------
__device__ __forceinline__ void fma2(unsigned long long& d,
                                     unsigned long long a, unsigned long long b) {
    asm("fma.rn.f32x2 %0, %1, %2, %0;" : "+l"(d) : "l"(a), "l"(b));
}
__device__ __forceinline__ float sum2(unsigned long long v) {
    float lo, hi;
    asm("mov.b64 {%0, %1}, %2;" : "=f"(lo), "=f"(hi) : "l"(v));
    return lo + hi;
}
__device__ __forceinline__ float sigm(float x) { return 1.0f / (1.0f + expf(-x)); }

__device__ __forceinline__ unsigned smem_u32(const void* p) {
    return (unsigned)__cvta_generic_to_shared(p);
}
__device__ __forceinline__ unsigned mapa_u32(unsigned addr, unsigned rank) {
    unsigned d;
    asm("mapa.shared::cluster.u32 %0, %1, %2;" : "=r"(d) : "r"(addr), "r"(rank));
    return d;
}
__device__ __forceinline__ void st_remote_f32(unsigned addr, float v) {
    asm volatile("st.shared::cluster.f32 [%0], %1;" :: "r"(addr), "f"(v));
}
__device__ __forceinline__ unsigned ctarank() {
    unsigned r; asm("mov.u32 %0, %%cluster_ctarank;" : "=r"(r)); return r;
}
#define CLUSTER_SYNC() do { \
    asm volatile("barrier.cluster.arrive.aligned;" ::: "memory"); \
    asm volatile("barrier.cluster.wait.aligned;"   ::: "memory"); } while (0)

__device__ __forceinline__ void cp16(unsigned dst, const float* src) {
    asm volatile("cp.async.cg.shared.global [%0], [%1], 16;" :: "r"(dst), "l"(src));
}
__device__ __forceinline__ void cp_commit() {
    asm volatile("cp.async.commit_group;" ::: "memory");
}
__device__ __forceinline__ void cp_wait1() {
    asm volatile("cp.async.wait_group 1;" ::: "memory");
}
__device__ __forceinline__ void cp_wait0() {
    asm volatile("cp.async.wait_group 0;" ::: "memory");
}

// =====================================================================
// gemm_kernel<K>: out[t][n] = sum_k A[t][k]*W[n][k] + b1[n] (+ b2[n]),
// t in [0,20). N-tile = 128 per block, 128 threads.
// Thread (lane, tg=warp): 4 n (lane + 32i) x 5 t (tg*5+j) register tile.
// A (20xK) staged once in smem; W streamed in 64-k chunks via double-
// buffered cp.async. A-loads are warp-uniform (tg const per warp) ->
// full-warp broadcast. W buf row stride 68 -> conflict-free LDS.128.
// a_sel: 0=Apar 1=g_comb 2=g_hl.  out_sel: 0=g_Xf 1=g_Xb 2=g_Xl 3=Opar.
// split>0: blocks >= split use the second parameter set (fused launches).
// =====================================================================
template<int K>
__device__ __forceinline__ void issue_chunk(unsigned bufu, const float* __restrict__ W,
                                            long nbase, int N, int ch, int tid) {
    #pragma unroll
    for (int i = 0; i < 16; i++) {
        int idx = i * 128 + tid;
        int r = idx >> 4, c4 = idx & 15;
        long n = nbase + r; if (n >= N) n = 0;     // clamp OOB rows (stores guarded)
        cp16(bufu + (unsigned)(r * 68 + c4 * 4) * 4u,
             W + n * K + ch * 64 + c4 * 4);
    }
    cp_commit();
}

template<int K>
__global__ void gemm_kernel(const float* __restrict__ Apar,
                            const float* __restrict__ W,
                            const float* __restrict__ b1,
                            const float* __restrict__ b2,
                            float* __restrict__ Opar,
                            int N, int a_sel, int out_sel, int rev,
                            int split,
                            const float* __restrict__ W2,
                            const float* __restrict__ b1_2,
                            const float* __restrict__ b2_2,
                            int out_sel2, int rev2)
{
    constexpr int NCH = K / 64;
    extern __shared__ float sm[];
    float* sB0 = sm;                       // 128 * 68
    float* sB1 = sm + 128 * 68;
    float* sA  = sm + 2 * 128 * 68;        // SEQ * K

    const int tid = threadIdx.x;           // 128
    long nbase = (long)blockIdx.x * 128;
    if (split && (int)blockIdx.x >= split) {
        W = W2; b1 = b1_2; b2 = b2_2; out_sel = out_sel2; rev = rev2;
        nbase = (long)((int)blockIdx.x - split) * 128;
    }

    const float* A = (a_sel == 0) ? Apar
                   : (a_sel == 1) ? &g_comb[0][0] : &g_hl[0][0];
    float* out = (out_sel == 0) ? &g_Xf[0][0]
               : (out_sel == 1) ? &g_Xb[0][0]
               : (out_sel == 2) ? &g_Xl[0][0] : Opar;

    // kick off W chunk prefetch first (DRAM latency head start)
    unsigned b0u = smem_u32(sB0), b1u = smem_u32(sB1);
    issue_chunk<K>(b0u, W, nbase, N, 0, tid);
    if (NCH > 1) issue_chunk<K>(b1u, W, nbase, N, 1, tid);

    // stage A (small; plain float4 loads)
    for (int idx = tid; idx < SEQ * (K / 4); idx += 128) {
        int t = idx / (K / 4), c4 = idx - t * (K / 4);
        const float4* src = reinterpret_cast<const float4*>(
            A + (long)(rev ? (SEQ - 1 - t) : t) * K) + c4;
        reinterpret_cast<float4*>(sA)[idx] = *src;
    }

    const int lane = tid & 31;
    const int tg   = tid >> 5;              // warp id == t-group (warp-uniform)
    const int t0   = tg * 5;

    unsigned long long acc[20];
    #pragma unroll
    for (int i = 0; i < 20; i++) acc[i] = 0ull;

    #pragma unroll 1
    for (int ch = 0; ch < NCH; ch++) {
        if (ch < NCH - 1) cp_wait1(); else cp_wait0();
        __syncthreads();
        const float* buf = (ch & 1) ? sB1 : sB0;

        #pragma unroll
        for (int k4 = 0; k4 < 16; k4++) {
            ulonglong2 w[4], a[5];
            #pragma unroll
            for (int i = 0; i < 4; i++)
                w[i] = *reinterpret_cast<const ulonglong2*>(&buf[(lane + 32 * i) * 68 + 4 * k4]);
            #pragma unroll
            for (int j = 0; j < 5; j++)     // warp-broadcast (tg uniform)
                a[j] = *reinterpret_cast<const ulonglong2*>(&sA[(t0 + j) * K + ch * 64 + 4 * k4]);
            #pragma unroll
            for (int i = 0; i < 4; i++)
                #pragma unroll
                for (int j = 0; j < 5; j++) {
                    fma2(acc[i * 5 + j], w[i].x, a[j].x);
                    fma2(acc[i * 5 + j], w[i].y, a[j].y);
                }
        }
        __syncthreads();
        if (ch + 2 < NCH)
            issue_chunk<K>((ch & 1) ? b1u : b0u, W, nbase, N, ch + 2, tid);
    }

    #pragma unroll
    for (int i = 0; i < 4; i++) {
        long n = nbase + lane + 32 * i;
        if (n < N) {
            float bias = b1[n] + (b2 ? b2[n] : 0.0f);
            #pragma unroll
            for (int j = 0; j < 5; j++)
                out[(long)(t0 + j) * N + n] = sum2(acc[i * 5 + j]) + bias;
        }
    }
}

// =====================================================================
// rec1: layer-1 LSTM, cluster of 4 CTAs per direction (grid 8).
// CTA rank s owns h-elements [32s,32s+32) and gate rows {g*128 + j}.
// Whh slice + X addends in smem; h exchanged via DSMEM double buffer;
// one cluster barrier per step.
// =====================================================================
__global__ void __cluster_dims__(4, 1, 1)
rec1_kernel(const float* __restrict__ Whh_f,
            const float* __restrict__ Whh_b,
            const float* __restrict__ h0f, const float* __restrict__ c0f,
            const float* __restrict__ h0b, const float* __restrict__ c0b)
{
    extern __shared__ float sm[];
    const int stride = H + 4;            // 132 -> conflict-free
    float* sW = sm;                      // 128 * 132
    float* sX = sm + 128 * stride;       // SEQ * 128
    __shared__ __align__(16) float sh[2][H];
    __shared__ float sg[128];
    __shared__ float sc[32];

    const int tid = threadIdx.x;         // 256
    const unsigned s = ctarank();        // 0..3
    const int d  = blockIdx.x >> 2;
    const int j0 = (int)s * 32;

    const float* Whh = d ? Whh_b : Whh_f;
    const float* h0  = d ? h0b : h0f;
    const float* c0  = d ? c0b : c0f;
    const float* X   = d ? &g_Xb[0][0] : &g_Xf[0][0];

    const float4* W4 = reinterpret_cast<const float4*>(Whh);
    for (int idx = tid; idx < 128 * 32; idx += 256) {
        int rr = idx >> 5, k4 = idx & 31;
        int row = ((rr >> 5) << 7) + j0 + (rr & 31);
        *reinterpret_cast<float4*>(&sW[rr * stride + 4 * k4]) = W4[row * 32 + k4];
    }
    for (int idx = tid; idx < SEQ * 128; idx += 256) {
        int ts = idx >> 7, tt = idx & 127;
        int row = ((tt >> 5) << 7) + j0 + (tt & 31);
        sX[idx] = X[ts * 4 * H + row];
    }
    if (tid < H)  sh[0][tid] = h0[tid];
    if (tid < 32) sc[tid]    = c0[j0 + tid];
    __syncthreads();

    int p = 0;
    for (int t = 0; t < SEQ; t++) {
        if (tid < 128) {
            const float* wr = &sW[tid * stride];
            const float* hb = sh[p];
            unsigned long long a[4] = {0ull, 0ull, 0ull, 0ull};
            #pragma unroll
            for (int k4 = 0; k4 < 32; k4++) {
                ulonglong2 w = *reinterpret_cast<const ulonglong2*>(&wr[4 * k4]);
                ulonglong2 h = *reinterpret_cast<const ulonglong2*>(&hb[4 * k4]);
                fma2(a[(k4 & 1) << 1],       w.x, h.x);
                fma2(a[((k4 & 1) << 1) | 1], w.y, h.y);
            }
            sg[tid] = sum2(a[0]) + sum2(a[1]) + sum2(a[2]) + sum2(a[3]) + sX[t * 128 + tid];
        }
        __syncthreads();
        if (tid < 32) {
            float gi = sg[tid], gf = sg[32 + tid], gg = sg[64 + tid], go = sg[96 + tid];
            float c = sigm(gf) * sc[tid] + sigm(gi) * tanhf(gg);
            float h = sigm(go) * tanhf(c);
            sc[tid] = c;
            unsigned la = smem_u32(&sh[p ^ 1][j0 + tid]);
            #pragma unroll
            for (unsigned r = 0; r < 4; r++) st_remote_f32(mapa_u32(la, r), h);
            g_comb[t][d * H + j0 + tid] = h;   // bwd kept in reversed-scan order
        }
        CLUSTER_SYNC();
        p ^= 1;
    }
}

// =====================================================================
// rec2: layer-2 LSTM (hidden 256), single cluster of 8 CTAs (grid 8).
// =====================================================================
__global__ void __cluster_dims__(8, 1, 1)
rec2_kernel(const float* __restrict__ Whh_l,
            const float* __restrict__ h0l,
            const float* __restrict__ c0l)
{
    extern __shared__ float sm[];
    const int K2 = 2 * H;                // 256
    const int stride = K2 + 4;           // 260
    float* sW = sm;                      // 128 * 260
    float* sX = sm + 128 * stride;       // SEQ * 128
    __shared__ __align__(16) float sh[2][2 * H];
    __shared__ float sg[128];
    __shared__ float sc[32];

    const int tid = threadIdx.x;         // 256
    const unsigned s = ctarank();        // 0..7
    const int j0 = (int)s * 32;

    const float4* W4 = reinterpret_cast<const float4*>(Whh_l);
    for (int idx = tid; idx < 128 * 64; idx += 256) {
        int rr = idx >> 6, k4 = idx & 63;
        int row = ((rr >> 5) << 8) + j0 + (rr & 31);
        *reinterpret_cast<float4*>(&sW[rr * stride + 4 * k4]) = W4[row * 64 + k4];
    }
    for (int idx = tid; idx < SEQ * 128; idx += 256) {
        int ts = idx >> 7, tt = idx & 127;
        int row = ((tt >> 5) << 8) + j0 + (tt & 31);
        sX[idx] = g_Xl[ts][row];
    }
    if (tid < K2) sh[0][tid] = h0l[tid];
    if (tid < 32) sc[tid]    = c0l[j0 + tid];
    __syncthreads();

    int p = 0;
    for (int t = 0; t < SEQ; t++) {
        if (tid < 128) {
            const float* wr = &sW[tid * stride];
            const float* hb = sh[p];
            unsigned long long a[8];
            #pragma unroll
            for (int i = 0; i < 8; i++) a[i] = 0ull;
            #pragma unroll
            for (int k4 = 0; k4 < 64; k4++) {
                ulonglong2 w = *reinterpret_cast<const ulonglong2*>(&wr[4 * k4]);
                ulonglong2 h = *reinterpret_cast<const ulonglong2*>(&hb[4 * k4]);
                fma2(a[(k4 & 3) << 1],       w.x, h.x);
                fma2(a[((k4 & 3) << 1) | 1], w.y, h.y);
            }
            float dot = sum2(a[0]) + sum2(a[1]) + sum2(a[2]) + sum2(a[3])
                      + sum2(a[4]) + sum2(a[5]) + sum2(a[6]) + sum2(a[7]);
            sg[tid] = dot + sX[t * 128 + tid];
        }
        __syncthreads();
        if (tid < 32) {
            float gi = sg[tid], gf = sg[32 + tid], gg = sg[64 + tid], go = sg[96 + tid];
            float c = sigm(gf) * sc[tid] + sigm(gi) * tanhf(gg);
            float h = sigm(go) * tanhf(c);
            sc[tid] = c;
            unsigned la = smem_u32(&sh[p ^ 1][j0 + tid]);
            #pragma unroll
            for (unsigned r = 0; r < 8; r++) st_remote_f32(mapa_u32(la, r), h);
            g_hl[t][j0 + tid] = h;
        }
        CLUSTER_SYNC();
        p ^= 1;
    }
}

// =====================================================================
extern "C" void kernel_launch(void* const* d_in, const int* in_sizes, int n_in,
                              void* d_out, int out_size)
{
    const float* x     = (const float*)d_in[0];
    const float* h0f   = (const float*)d_in[1];
    const float* c0f   = (const float*)d_in[2];
    const float* h0b   = (const float*)d_in[3];
    const float* c0b   = (const float*)d_in[4];
    const float* h0l   = (const float*)d_in[5];
    const float* c0l   = (const float*)d_in[6];
    const float* Wih_f = (const float*)d_in[7];
    const float* Whh_f = (const float*)d_in[8];
    const float* bih_f = (const float*)d_in[9];
    const float* bhh_f = (const float*)d_in[10];
    const float* Wih_b = (const float*)d_in[11];
    const float* Whh_b = (const float*)d_in[12];
    const float* bih_b = (const float*)d_in[13];
    const float* bhh_b = (const float*)d_in[14];
    const float* Wih_l = (const float*)d_in[15];
    const float* Whh_l = (const float*)d_in[16];
    const float* bih_l = (const float*)d_in[17];
    const float* bhh_l = (const float*)d_in[18];
    const float* Wlin  = (const float*)d_in[19];
    const float* blin  = (const float*)d_in[20];
    float* out = (float*)d_out;

    const int smem_g128 = (2 * 128 * 68 + SEQ * 128) * 4;    // 79872
    const int smem_g256 = (2 * 128 * 68 + SEQ * 256) * 4;    // 90112
    const int smem_r1   = (128 * (128 + 4) + SEQ * 128) * 4; // 77824
    const int smem_r2   = (128 * (256 + 4) + SEQ * 128) * 4; // 143360

    cudaFuncSetAttribute(gemm_kernel<128>, cudaFuncAttributeMaxDynamicSharedMemorySize, smem_g128);
    cudaFuncSetAttribute(gemm_kernel<256>, cudaFuncAttributeMaxDynamicSharedMemorySize, smem_g256);
    cudaFuncSetAttribute(rec1_kernel,      cudaFuncAttributeMaxDynamicSharedMemorySize, smem_r1);
    cudaFuncSetAttribute(rec2_kernel,      cudaFuncAttributeMaxDynamicSharedMemorySize, smem_r2);

    // 1) fused layer-1 x-projections: blocks 0-3 fwd, 4-7 bwd(rev)
    gemm_kernel<128><<<8, 128, smem_g128>>>(x, Wih_f, bih_f, bhh_f, nullptr,
                                            4 * H, /*a*/0, /*out*/0, /*rev*/0,
                                            /*split*/4, Wih_b, bih_b, bhh_b,
                                            /*out2*/1, /*rev2*/1);
    // 2) layer-1 recurrences (2 clusters of 4)
    rec1_kernel<<<8, 256, smem_r1>>>(Whh_f, Whh_b, h0f, c0f, h0b, c0b);
    // 3) layer-2 x-projection
    gemm_kernel<256><<<8, 128, smem_g256>>>(nullptr, Wih_l, bih_l, bhh_l, nullptr,
                                            8 * H, 1, 2, 0, 0,
                                            nullptr, nullptr, nullptr, 0, 0);
    // 4) layer-2 recurrence (1 cluster of 8)
    rec2_kernel<<<8, 256, smem_r2>>>(Whh_l, h0l, c0l);
    // 5) final linear head: [20,100000] = hl @ Wlin^T + blin
    gemm_kernel<256><<<(NC + 127) / 128, 128, smem_g256>>>(nullptr, Wlin, blin, nullptr,
                                                           out, NC, 2, 3, 0, 0,
                                                           nullptr, nullptr, nullptr, 0, 0);
}

// round 11
// speedup vs baseline: 2.5099x; 1.2413x over previous
#include <cuda_runtime.h>
#include <math.h>

#define SEQ 20
#define H   128
#define NC  100000

// ---------------- device scratch (no allocations allowed) ----------------
__device__ float g_Xf[SEQ][4*H];          // x @ Wih_f^T + bih_f + bhh_f
__device__ float g_Xb[SEQ][4*H];          // x[rev] @ Wih_b^T + biases
__device__ float g_comb[SEQ][2*H];        // [fwd_h, bwd_h]
__device__ float g_Xl[SEQ][8*H];          // comb @ Wih_l^T + biases
__device__ float g_hl[SEQ][2*H];          // layer-2 hidden states

// ---------------- helpers ----------------
__device__ __forceinline__ void fma2(unsigned long long& d,
                                     unsigned long long a, unsigned long long b) {
    asm("fma.rn.f32x2 %0, %1, %2, %0;" : "+l"(d) : "l"(a), "l"(b));
}
__device__ __forceinline__ float sum2(unsigned long long v) {
    float lo, hi;
    asm("mov.b64 {%0, %1}, %2;" : "=f"(lo), "=f"(hi) : "l"(v));
    return lo + hi;
}
__device__ __forceinline__ float sigm(float x) { return 1.0f / (1.0f + expf(-x)); }

__device__ __forceinline__ unsigned smem_u32(const void* p) {
    return (unsigned)__cvta_generic_to_shared(p);
}
__device__ __forceinline__ unsigned mapa_u32(unsigned addr, unsigned rank) {
    unsigned d;
    asm("mapa.shared::cluster.u32 %0, %1, %2;" : "=r"(d) : "r"(addr), "r"(rank));
    return d;
}
__device__ __forceinline__ unsigned ctarank() {
    unsigned r; asm("mov.u32 %0, %%cluster_ctarank;" : "=r"(r)); return r;
}
#define CLUSTER_SYNC() do { \
    asm volatile("barrier.cluster.arrive.aligned;" ::: "memory"); \
    asm volatile("barrier.cluster.wait.aligned;"   ::: "memory"); } while (0)

// ---- st.async + mbarrier tx sync (replaces cluster barrier in rec loops) ----
__device__ __forceinline__ void mbar_init(unsigned addr, unsigned count) {
    asm volatile("mbarrier.init.shared.b64 [%0], %1;" :: "r"(addr), "r"(count) : "memory");
}
__device__ __forceinline__ void mbar_expect(unsigned addr, unsigned bytes) {
    asm volatile("mbarrier.arrive.expect_tx.shared.b64 _, [%0], %1;"
                 :: "r"(addr), "r"(bytes) : "memory");
}
__device__ __forceinline__ void mbar_wait(unsigned addr, unsigned parity) {
    asm volatile(
        "{\n\t"
        ".reg .pred P;\n\t"
        "LW%=:\n\t"
        "mbarrier.try_wait.parity.acquire.cluster.shared::cta.b64 P, [%0], %1, 0x989680;\n\t"
        "@P bra LD%=;\n\t"
        "bra LW%=;\n\t"
        "LD%=:\n\t"
        "}"
        :: "r"(addr), "r"(parity) : "memory");
}
__device__ __forceinline__ void st_async_f32(unsigned raddr, float v, unsigned rmbar) {
    asm volatile("st.async.shared::cluster.mbarrier::complete_tx::bytes.b32 [%0], %1, [%2];"
                 :: "r"(raddr), "r"(__float_as_uint(v)), "r"(rmbar) : "memory");
}

__device__ __forceinline__ void cp16(unsigned dst, const float* src) {
    asm volatile("cp.async.cg.shared.global [%0], [%1], 16;" :: "r"(dst), "l"(src));
}
__device__ __forceinline__ void cp_commit() {
    asm volatile("cp.async.commit_group;" ::: "memory");
}
__device__ __forceinline__ void cp_wait1() {
    asm volatile("cp.async.wait_group 1;" ::: "memory");
}
__device__ __forceinline__ void cp_wait0() {
    asm volatile("cp.async.wait_group 0;" ::: "memory");
}

// =====================================================================
// gemm_kernel<K>: out[t][n] = sum_k A[t][k]*W[n][k] + b1[n] (+ b2[n]).
// (unchanged from R10 — 4n x 5t register tile, cp.async double buffer)
// =====================================================================
template<int K>
__device__ __forceinline__ void issue_chunk(unsigned bufu, const float* __restrict__ W,
                                            long nbase, int N, int ch, int tid) {
    #pragma unroll
    for (int i = 0; i < 16; i++) {
        int idx = i * 128 + tid;
        int r = idx >> 4, c4 = idx & 15;
        long n = nbase + r; if (n >= N) n = 0;
        cp16(bufu + (unsigned)(r * 68 + c4 * 4) * 4u,
             W + n * K + ch * 64 + c4 * 4);
    }
    cp_commit();
}

template<int K>
__global__ void gemm_kernel(const float* __restrict__ Apar,
                            const float* __restrict__ W,
                            const float* __restrict__ b1,
                            const float* __restrict__ b2,
                            float* __restrict__ Opar,
                            int N, int a_sel, int out_sel, int rev,
                            int split,
                            const float* __restrict__ W2,
                            const float* __restrict__ b1_2,
                            const float* __restrict__ b2_2,
                            int out_sel2, int rev2)
{
    constexpr int NCH = K / 64;
    extern __shared__ float sm[];
    float* sB0 = sm;                       // 128 * 68
    float* sB1 = sm + 128 * 68;
    float* sA  = sm + 2 * 128 * 68;        // SEQ * K

    const int tid = threadIdx.x;           // 128
    long nbase = (long)blockIdx.x * 128;
    if (split && (int)blockIdx.x >= split) {
        W = W2; b1 = b1_2; b2 = b2_2; out_sel = out_sel2; rev = rev2;
        nbase = (long)((int)blockIdx.x - split) * 128;
    }

    const float* A = (a_sel == 0) ? Apar
                   : (a_sel == 1) ? &g_comb[0][0] : &g_hl[0][0];
    float* out = (out_sel == 0) ? &g_Xf[0][0]
               : (out_sel == 1) ? &g_Xb[0][0]
               : (out_sel == 2) ? &g_Xl[0][0] : Opar;

    unsigned b0u = smem_u32(sB0), b1u = smem_u32(sB1);
    issue_chunk<K>(b0u, W, nbase, N, 0, tid);
    if (NCH > 1) issue_chunk<K>(b1u, W, nbase, N, 1, tid);

    for (int idx = tid; idx < SEQ * (K / 4); idx += 128) {
        int t = idx / (K / 4), c4 = idx - t * (K / 4);
        const float4* src = reinterpret_cast<const float4*>(
            A + (long)(rev ? (SEQ - 1 - t) : t) * K) + c4;
        reinterpret_cast<float4*>(sA)[idx] = *src;
    }

    const int lane = tid & 31;
    const int tg   = tid >> 5;
    const int t0   = tg * 5;

    unsigned long long acc[20];
    #pragma unroll
    for (int i = 0; i < 20; i++) acc[i] = 0ull;

    #pragma unroll 1
    for (int ch = 0; ch < NCH; ch++) {
        if (ch < NCH - 1) cp_wait1(); else cp_wait0();
        __syncthreads();
        const float* buf = (ch & 1) ? sB1 : sB0;

        #pragma unroll
        for (int k4 = 0; k4 < 16; k4++) {
            ulonglong2 w[4], a[5];
            #pragma unroll
            for (int i = 0; i < 4; i++)
                w[i] = *reinterpret_cast<const ulonglong2*>(&buf[(lane + 32 * i) * 68 + 4 * k4]);
            #pragma unroll
            for (int j = 0; j < 5; j++)
                a[j] = *reinterpret_cast<const ulonglong2*>(&sA[(t0 + j) * K + ch * 64 + 4 * k4]);
            #pragma unroll
            for (int i = 0; i < 4; i++)
                #pragma unroll
                for (int j = 0; j < 5; j++) {
                    fma2(acc[i * 5 + j], w[i].x, a[j].x);
                    fma2(acc[i * 5 + j], w[i].y, a[j].y);
                }
        }
        __syncthreads();
        if (ch + 2 < NCH)
            issue_chunk<K>((ch & 1) ? b1u : b0u, W, nbase, N, ch + 2, tid);
    }

    #pragma unroll
    for (int i = 0; i < 4; i++) {
        long n = nbase + lane + 32 * i;
        if (n < N) {
            float bias = b1[n] + (b2 ? b2[n] : 0.0f);
            #pragma unroll
            for (int j = 0; j < 5; j++)
                out[(long)(t0 + j) * N + n] = sum2(acc[i * 5 + j]) + bias;
        }
    }
}

// =====================================================================
// rec1: layer-1 LSTM. 2 clusters of 4 CTAs (grid 8), 256 threads/CTA.
// Whh rows live in REGISTERS: thread pair (2m,2m+1) owns gate row m
// (64 floats each half). h exchanged via st.async into peers' double-
// buffered sh[]; mbarrier tx-wait replaces the cluster barrier.
// =====================================================================
__global__ void __cluster_dims__(4, 1, 1) __launch_bounds__(256, 1)
rec1_kernel(const float* __restrict__ Whh_f,
            const float* __restrict__ Whh_b,
            const float* __restrict__ h0f, const float* __restrict__ c0f,
            const float* __restrict__ h0b, const float* __restrict__ c0b)
{
    __shared__ float sX[SEQ * 128];
    __shared__ __align__(16) float sh[2][H];
    __shared__ float sg[128];
    __shared__ float sc[32];
    __shared__ __align__(8) unsigned long long mbar[2];

    const int tid = threadIdx.x;         // 256
    const unsigned s = ctarank();        // 0..3
    const int d  = blockIdx.x >> 2;
    const int j0 = (int)s * 32;

    const float* Whh = d ? Whh_b : Whh_f;
    const float* h0  = d ? h0b : h0f;
    const float* c0  = d ? c0b : c0f;
    const float* X   = d ? &g_Xb[0][0] : &g_Xf[0][0];

    const int rr = tid >> 1;                         // local gate row 0..127
    const int kh = (tid & 1) * 64;                   // k half
    const int grow = ((rr >> 5) << 7) + j0 + (rr & 31);

    // W rows -> registers (32 f32x2 per thread)
    unsigned long long w[32];
    {
        const ulonglong2* wg = reinterpret_cast<const ulonglong2*>(Whh + (long)grow * H + kh);
        #pragma unroll
        for (int i = 0; i < 16; i++) { ulonglong2 v = wg[i]; w[2*i] = v.x; w[2*i+1] = v.y; }
    }
    for (int idx = tid; idx < SEQ * 128; idx += 256) {
        int ts = idx >> 7, tt = idx & 127;
        int row = ((tt >> 5) << 7) + j0 + (tt & 31);
        sX[idx] = X[ts * 4 * H + row];
    }
    if (tid < H)  sh[0][tid] = h0[tid];
    if (tid < 32) sc[tid]    = c0[j0 + tid];
    if (tid == 0) { mbar_init(smem_u32(&mbar[0]), 1); mbar_init(smem_u32(&mbar[1]), 1); }
    __syncthreads();
    CLUSTER_SYNC();                       // mbar init visible before any st.async

    int ph0 = 0, ph1 = 0;
    #pragma unroll 1
    for (int t = 0; t < SEQ; t++) {
        if (t > 0) {
            int b = t & 1;
            mbar_wait(smem_u32(&mbar[b]), b ? ph1 : ph0);
            if (b) ph1 ^= 1; else ph0 ^= 1;
        }
        if (tid == 0 && t + 1 < SEQ) mbar_expect(smem_u32(&mbar[(t+1) & 1]), 4 * 32 * 4);

        const float* hb = sh[t & 1];
        unsigned long long a0 = 0ull, a1 = 0ull;
        #pragma unroll
        for (int i = 0; i < 16; i++) {
            ulonglong2 h2 = *reinterpret_cast<const ulonglong2*>(&hb[kh + 4 * i]);
            fma2(a0, w[2*i],   h2.x);
            fma2(a1, w[2*i+1], h2.y);
        }
        float part = sum2(a0) + sum2(a1);
        part += __shfl_xor_sync(0xffffffffu, part, 1);
        if (!(tid & 1)) sg[rr] = part + sX[t * 128 + rr];
        __syncthreads();

        if (tid < 32) {
            float gi = sg[tid], gf = sg[32 + tid], gg = sg[64 + tid], go = sg[96 + tid];
            float c = sigm(gf) * sc[tid] + sigm(gi) * tanhf(gg);
            float h = sigm(go) * tanhf(c);
            sc[tid] = c;
            if (t + 1 < SEQ) {
                unsigned la = smem_u32(&sh[(t+1) & 1][j0 + tid]);
                unsigned lm = smem_u32(&mbar[(t+1) & 1]);
                #pragma unroll
                for (unsigned r = 0; r < 4; r++)
                    st_async_f32(mapa_u32(la, r), h, mapa_u32(lm, r));
            }
            g_comb[t][d * H + j0 + tid] = h;
        }
        // next iteration's mbar_wait forms the rendezvous; no barrier here
    }
    CLUSTER_SYNC();
}

// =====================================================================
// rec2: layer-2 LSTM (hidden 256). Single cluster of 8 CTAs, 256 thr.
// Thread pair owns one of 128 gate rows (128 floats each half in regs).
// =====================================================================
__global__ void __cluster_dims__(8, 1, 1) __launch_bounds__(256, 1)
rec2_kernel(const float* __restrict__ Whh_l,
            const float* __restrict__ h0l,
            const float* __restrict__ c0l)
{
    const int K2 = 2 * H;                // 256
    __shared__ float sX[SEQ * 128];
    __shared__ __align__(16) float sh[2][2 * H];
    __shared__ float sg[128];
    __shared__ float sc[32];
    __shared__ __align__(8) unsigned long long mbar[2];

    const int tid = threadIdx.x;         // 256
    const unsigned s = ctarank();        // 0..7
    const int j0 = (int)s * 32;

    const int rr = tid >> 1;                          // local gate row 0..127
    const int kh = (tid & 1) * 128;                   // k half
    const int grow = ((rr >> 5) << 8) + j0 + (rr & 31);

    unsigned long long w[64];
    {
        const ulonglong2* wg = reinterpret_cast<const ulonglong2*>(Whh_l + (long)grow * K2 + kh);
        #pragma unroll
        for (int i = 0; i < 32; i++) { ulonglong2 v = wg[i]; w[2*i] = v.x; w[2*i+1] = v.y; }
    }
    for (int idx = tid; idx < SEQ * 128; idx += 256) {
        int ts = idx >> 7, tt = idx & 127;
        int row = ((tt >> 5) << 8) + j0 + (tt & 31);
        sX[idx] = g_Xl[ts][row];
    }
    if (tid < K2) sh[0][tid] = h0l[tid];
    if (tid < 32) sc[tid]    = c0l[j0 + tid];
    if (tid == 0) { mbar_init(smem_u32(&mbar[0]), 1); mbar_init(smem_u32(&mbar[1]), 1); }
    __syncthreads();
    CLUSTER_SYNC();

    int ph0 = 0, ph1 = 0;
    #pragma unroll 1
    for (int t = 0; t < SEQ; t++) {
        if (t > 0) {
            int b = t & 1;
            mbar_wait(smem_u32(&mbar[b]), b ? ph1 : ph0);
            if (b) ph1 ^= 1; else ph0 ^= 1;
        }
        if (tid == 0 && t + 1 < SEQ) mbar_expect(smem_u32(&mbar[(t+1) & 1]), 8 * 32 * 4);

        const float* hb = sh[t & 1];
        unsigned long long a0 = 0ull, a1 = 0ull, a2 = 0ull, a3 = 0ull;
        #pragma unroll
        for (int i = 0; i < 32; i++) {
            ulonglong2 h2 = *reinterpret_cast<const ulonglong2*>(&hb[kh + 4 * i]);
            if (i & 1) { fma2(a2, w[2*i], h2.x); fma2(a3, w[2*i+1], h2.y); }
            else       { fma2(a0, w[2*i], h2.x); fma2(a1, w[2*i+1], h2.y); }
        }
        float part = sum2(a0) + sum2(a1) + sum2(a2) + sum2(a3);
        part += __shfl_xor_sync(0xffffffffu, part, 1);
        if (!(tid & 1)) sg[rr] = part + sX[t * 128 + rr];
        __syncthreads();

        if (tid < 32) {
            float gi = sg[tid], gf = sg[32 + tid], gg = sg[64 + tid], go = sg[96 + tid];
            float c = sigm(gf) * sc[tid] + sigm(gi) * tanhf(gg);
            float h = sigm(go) * tanhf(c);
            sc[tid] = c;
            if (t + 1 < SEQ) {
                unsigned la = smem_u32(&sh[(t+1) & 1][j0 + tid]);
                unsigned lm = smem_u32(&mbar[(t+1) & 1]);
                #pragma unroll
                for (unsigned r = 0; r < 8; r++)
                    st_async_f32(mapa_u32(la, r), h, mapa_u32(lm, r));
            }
            g_hl[t][j0 + tid] = h;
        }
    }
    CLUSTER_SYNC();
}

// =====================================================================
extern "C" void kernel_launch(void* const* d_in, const int* in_sizes, int n_in,
                              void* d_out, int out_size)
{
    const float* x     = (const float*)d_in[0];
    const float* h0f   = (const float*)d_in[1];
    const float* c0f   = (const float*)d_in[2];
    const float* h0b   = (const float*)d_in[3];
    const float* c0b   = (const float*)d_in[4];
    const float* h0l   = (const float*)d_in[5];
    const float* c0l   = (const float*)d_in[6];
    const float* Wih_f = (const float*)d_in[7];
    const float* Whh_f = (const float*)d_in[8];
    const float* bih_f = (const float*)d_in[9];
    const float* bhh_f = (const float*)d_in[10];
    const float* Wih_b = (const float*)d_in[11];
    const float* Whh_b = (const float*)d_in[12];
    const float* bih_b = (const float*)d_in[13];
    const float* bhh_b = (const float*)d_in[14];
    const float* Wih_l = (const float*)d_in[15];
    const float* Whh_l = (const float*)d_in[16];
    const float* bih_l = (const float*)d_in[17];
    const float* bhh_l = (const float*)d_in[18];
    const float* Wlin  = (const float*)d_in[19];
    const float* blin  = (const float*)d_in[20];
    float* out = (float*)d_out;

    const int smem_g128 = (2 * 128 * 68 + SEQ * 128) * 4;    // 79872
    const int smem_g256 = (2 * 128 * 68 + SEQ * 256) * 4;    // 90112

    cudaFuncSetAttribute(gemm_kernel<128>, cudaFuncAttributeMaxDynamicSharedMemorySize, smem_g128);
    cudaFuncSetAttribute(gemm_kernel<256>, cudaFuncAttributeMaxDynamicSharedMemorySize, smem_g256);

    // 1) fused layer-1 x-projections: blocks 0-3 fwd, 4-7 bwd(rev)
    gemm_kernel<128><<<8, 128, smem_g128>>>(x, Wih_f, bih_f, bhh_f, nullptr,
                                            4 * H, 0, 0, 0,
                                            4, Wih_b, bih_b, bhh_b, 1, 1);
    // 2) layer-1 recurrences (2 clusters of 4)
    rec1_kernel<<<8, 256>>>(Whh_f, Whh_b, h0f, c0f, h0b, c0b);
    // 3) layer-2 x-projection
    gemm_kernel<256><<<8, 128, smem_g256>>>(nullptr, Wih_l, bih_l, bhh_l, nullptr,
                                            8 * H, 1, 2, 0, 0,
                                            nullptr, nullptr, nullptr, 0, 0);
    // 4) layer-2 recurrence (1 cluster of 8)
    rec2_kernel<<<8, 256>>>(Whh_l, h0l, c0l);
    // 5) final linear head: [20,100000] = hl @ Wlin^T + blin
    gemm_kernel<256><<<(NC + 127) / 128, 128, smem_g256>>>(nullptr, Wlin, blin, nullptr,
                                                           out, NC, 2, 3, 0, 0,
                                                           nullptr, nullptr, nullptr, 0, 0);
}